// round 3
// baseline (speedup 1.0000x reference)
#include <cuda_runtime.h>
#include <stdint.h>

#define NANCH 8732
#define NCLS 21
#define TOPK 200
#define CONF_TH 0.01f
#define NMS_TH 0.045f
#define MAXB 128

// Scratch (no device allocs allowed):
__device__ float g_probsT[(size_t)MAXB * NCLS * NANCH];   // masked softmax probs, [B,C,N]
__device__ float g_boxes[(size_t)MAXB * NANCH * 4];       // decoded corner boxes, [B,N,4]

// ---------------------------------------------------------------------------
// Kernel A: softmax over classes + SSD box decode. One thread per (b,n),
// conf staged through smem for coalesced global loads.
// ---------------------------------------------------------------------------
__global__ void __launch_bounds__(256) softmax_decode_kernel(
        const float* __restrict__ loc,
        const float* __restrict__ conf,
        const float* __restrict__ anchors,
        int total) {
    __shared__ float sc[256 * NCLS];
    int base = blockIdx.x * 256;

    // coalesced conf load for this block's 256 anchors
    int gbase = base * NCLS;
    int navail = min(256 * NCLS, total * NCLS - gbase);
    for (int i = threadIdx.x; i < navail; i += 256)
        sc[i] = conf[gbase + i];
    __syncthreads();

    int idx = base + threadIdx.x;
    if (idx >= total) return;
    int b = idx / NANCH;
    int n = idx - b * NANCH;

    float v[NCLS];
    float mx = -1e30f;
#pragma unroll
    for (int c = 0; c < NCLS; c++) { v[c] = sc[threadIdx.x * NCLS + c]; mx = fmaxf(mx, v[c]); }
    float s = 0.0f;
#pragma unroll
    for (int c = 0; c < NCLS; c++) { v[c] = expf(v[c] - mx); s += v[c]; }
    float inv = 1.0f / s;
#pragma unroll
    for (int c = 0; c < NCLS; c++) {
        float p = v[c] * inv;
        g_probsT[((size_t)b * NCLS + c) * NANCH + n] = (p > CONF_TH) ? p : 0.0f;
    }

    float4 l4 = __ldg((const float4*)(loc) + idx);
    float4 a4 = __ldg((const float4*)(anchors) + n);
    float cx = a4.x + l4.x * 0.1f * a4.z;
    float cy = a4.y + l4.y * 0.1f * a4.w;
    float w  = a4.z * expf(l4.z * 0.2f);
    float h  = a4.w * expf(l4.w * 0.2f);
    float4 bb;
    bb.x = cx - 0.5f * w;
    bb.y = cy - 0.5f * h;
    bb.z = cx + 0.5f * w;
    bb.w = cy + 0.5f * h;
    ((float4*)g_boxes)[idx] = bb;
}

// ---------------------------------------------------------------------------
// Kernel B: per (b, class) task — radix-select top-200 (warp-scan), bitonic
// sort via shfl, IoU bitmask precompute, serial bitwise keep propagation.
// One CTA of 256 threads per task.
// ---------------------------------------------------------------------------
__global__ void __launch_bounds__(256) topk_nms_kernel(float* __restrict__ out) {
    int task = blockIdx.x;
    int b = task / (NCLS - 1);
    int c = task % (NCLS - 1) + 1;   // skip background class 0
    int tid = threadIdx.x;
    int lane = tid & 31, wrp = tid >> 5;

    // Reused shared buffer:
    //   phase 1: unsigned sbits[8732]                     (34928 B)
    //   phase 2: float4 sbx4[200] | float sarea[200] | unsigned sup[200*7]
    __shared__ __align__(16) unsigned sbuf[NANCH];
    __shared__ unsigned hist[256];
    __shared__ unsigned long long skey[256];
    __shared__ unsigned keepmask[8];
    __shared__ unsigned wcnt[8], woff[8];
    __shared__ unsigned k_sh, bin_sh, cnt_sh;

    unsigned* sbits = sbuf;
    float4*   sbx4  = (float4*)sbuf;                      // [200]
    float*    sarea = (float*)(sbuf + 800);               // [200]
    unsigned* supw  = sbuf + 1000;                        // [200*7]

    // Load masked scores (coalesced: [B,C,N] layout). Scores >= 0 so bit
    // pattern order == value order.
    const float* sp = g_probsT + ((size_t)b * NCLS + c) * NANCH;
    for (int n = tid; n < NANCH; n += 256)
        sbits[n] = __float_as_uint(sp[n]);
    if (tid == 0) { k_sh = TOPK; cnt_sh = 0u; bin_sh = 0u; }
    hist[tid] = 0u;
    skey[tid] = 0ULL;
    __syncthreads();

    // --- 4-pass radix select: find bit pattern P of the TOPK-th largest ---
    unsigned prefix = 0u, pmask = 0u;
#pragma unroll
    for (int pass = 0; pass < 4; pass++) {
        int shift = 24 - 8 * pass;
        for (int n = tid; n < NANCH; n += 256) {
            unsigned u = sbits[n];
            if (u != 0u && (u & pmask) == prefix)
                atomicAdd(&hist[(u >> shift) & 255u], 1u);
        }
        __syncthreads();
        if (tid < 32) {
            // warp 0: suffix scan of 256 bins (8 bins per lane), find pivot bin
            unsigned local[8];
            unsigned lsum = 0;
#pragma unroll
            for (int j = 0; j < 8; j++) {
                local[j] = hist[tid * 8 + j];
                lsum += local[j];
                hist[tid * 8 + j] = 0u;       // re-zero for next pass
            }
            unsigned ssum = lsum;
#pragma unroll
            for (int off = 1; off < 32; off <<= 1) {
                unsigned vv = __shfl_down_sync(0xffffffffu, ssum, off);
                if (tid + off < 32) ssum += vv;
            }
            unsigned k = k_sh;
            unsigned run = ssum - lsum;        // suffix count of bins > tid*8+7
            unsigned fbin = 0u, fk = 0u;
#pragma unroll
            for (int j = 7; j >= 0; j--) {
                unsigned prev = run;
                run += local[j];
                if (run >= k && prev < k) { fbin = tid * 8 + j; fk = k - prev; }
            }
            unsigned bmax = __reduce_max_sync(0xffffffffu, fbin);
            unsigned kmax = __reduce_max_sync(0xffffffffu, fk);
            if (tid == 0) {
                bin_sh = bmax;                 // written EVERY pass (0 if not found)
                if (kmax) k_sh = kmax;
            }
        }
        __syncthreads();
        // NOTE: no reset of bin_sh here — lane 0 rewrites it every pass.
        // (A reset write racing these reads was the R2 correctness bug.)
        prefix |= bin_sh << shift;
        pmask  |= 255u << shift;
        __syncthreads();
    }
    unsigned Plo = (prefix > 0u) ? prefix : 1u;   // never collect exact zeros

    // --- collect candidates >= pivot (<=256 with prob ~1) ---
    for (int n = tid; n < NANCH; n += 256) {
        unsigned u = sbits[n];
        if (u >= Plo) {
            unsigned p = atomicAdd(&cnt_sh, 1u);
            if (p < 256u)
                skey[p] = ((unsigned long long)u << 32) | (unsigned)(~n);
        }
    }
    __syncthreads();
    // sbits region is DEAD from here: reuse as sbx4 / sarea / supw.

    // --- bitonic sort 256 keys descending (value desc, idx asc on ties) ---
    unsigned long long key = skey[tid];
#pragma unroll
    for (int ks = 2; ks <= 256; ks <<= 1) {
#pragma unroll
        for (int st = ks >> 1; st > 0; st >>= 1) {
            bool up = ((tid & ks) == 0);
            unsigned long long other;
            if (st >= 32) {
                skey[tid] = key;
                __syncthreads();
                other = skey[tid ^ st];
                __syncthreads();
            } else {
                other = __shfl_xor_sync(0xffffffffu, key, st);
            }
            bool iLow = ((tid & st) == 0);
            bool takeMax = (iLow == up);
            bool otherBigger = (other > key);
            if (takeMax == otherBigger) key = other;
        }
    }

    // --- fetch boxes for selected top-200 ---
    float score = 0.f, x1 = 0.f, y1 = 0.f, x2 = 0.f, y2 = 0.f, area = 0.f;
    int keepf = 0;
    if (tid < TOPK) {
        unsigned vb = (unsigned)(key >> 32);
        if (vb != 0u) {
            unsigned n = ~(unsigned)(key & 0xFFFFFFFFu);
            score = __uint_as_float(vb);
            float4 bp = ((const float4*)g_boxes)[(size_t)b * NANCH + n];
            x1 = bp.x; y1 = bp.y; x2 = bp.z; y2 = bp.w;
            area = (x2 - x1) * (y2 - y1);
            keepf = 1;
        }
        float4 bb; bb.x = x1; bb.y = y1; bb.z = x2; bb.w = y2;
        sbx4[tid] = bb;
        sarea[tid] = area;
    }
    // initial keep bitmask (per-warp ballot; warps 0..6 cover 0..199)
    {
        unsigned bal = __ballot_sync(0xffffffffu, keepf);
        if (lane == 0 && wrp < 7) keepmask[wrp] = bal;
    }
    __syncthreads();

    // --- precompute suppression bitmask rows: sup[i] bit j set iff
    //     j > i && iou(i,j) > NMS_TH. Parallel, barrier-free. ---
    if (tid < TOPK) {
#pragma unroll
        for (int w = 0; w < 7; w++) {
            unsigned m = 0u;
#pragma unroll
            for (int bit = 0; bit < 32; bit++) {
                int j = w * 32 + bit;
                if (j < TOPK) {
                    float4 ob = sbx4[j];
                    float oa = sarea[j];
                    float ix1 = fmaxf(x1, ob.x);
                    float iy1 = fmaxf(y1, ob.y);
                    float ix2 = fminf(x2, ob.z);
                    float iy2 = fminf(y2, ob.w);
                    float iw = fmaxf(ix2 - ix1, 0.0f);
                    float ih = fmaxf(iy2 - iy1, 0.0f);
                    float inter = iw * ih;
                    float iou = inter / (area + oa - inter + 1e-12f);
                    if (j > tid && iou > NMS_TH) m |= (1u << bit);
                }
            }
            supw[tid * 7 + w] = m;
        }
    }
    __syncthreads();

    // --- serial keep propagation: one thread, bitwise, fully unrolled ---
    if (tid == 0) {
        unsigned kk[7];
#pragma unroll
        for (int w = 0; w < 7; w++) kk[w] = keepmask[w];
#pragma unroll
        for (int w = 0; w < 7; w++) {
#pragma unroll
            for (int bit = 0; bit < 32; bit++) {
                int i = w * 32 + bit;
                if (i < TOPK) {
                    if (kk[w] & (1u << bit)) {
                        const unsigned* row = &supw[i * 7];
#pragma unroll
                        for (int ww = 0; ww < 7; ww++) kk[ww] &= ~row[ww];
                    }
                }
            }
        }
#pragma unroll
        for (int w = 0; w < 7; w++) keepmask[w] = kk[w];
    }
    __syncthreads();

    // --- pack kept entries to the front (stable) and write output ---
    int keepv = 0;
    if (tid < TOPK) keepv = (keepmask[tid >> 5] >> (tid & 31)) & 1;
    unsigned bal = __ballot_sync(0xffffffffu, keepv);
    if (lane == 0) wcnt[wrp] = __popc(bal);
    __syncthreads();
    if (tid == 0) {
        unsigned run = 0;
        for (int i = 0; i < 8; i++) { woff[i] = run; run += wcnt[i]; }
    }
    __syncthreads();
    if (keepv) {
        int pos = woff[wrp] + __popc(bal & ((1u << lane) - 1u));
        float* orow = out + ((((size_t)b * NCLS + c) * TOPK) + pos) * 5;
        orow[0] = score; orow[1] = x1; orow[2] = y1; orow[3] = x2; orow[4] = y2;
    }
}

// ---------------------------------------------------------------------------
extern "C" void kernel_launch(void* const* d_in, const int* in_sizes, int n_in,
                              void* d_out, int out_size) {
    const float* loc     = (const float*)d_in[0];  // [B,N,4]
    const float* conf    = (const float*)d_in[1];  // [B,N,21]
    const float* anchors = (const float*)d_in[2];  // [N,4]
    float* out = (float*)d_out;                    // [B,21,200,5]

    int total = in_sizes[0] / 4;          // B*N
    int B = total / NANCH;
    if (B > MAXB) B = MAXB;
    total = B * NANCH;

    cudaMemsetAsync(d_out, 0, (size_t)out_size * sizeof(float), 0);

    softmax_decode_kernel<<<(total + 255) / 256, 256>>>(loc, conf, anchors, total);
    topk_nms_kernel<<<B * (NCLS - 1), 256>>>(out);
}

// round 4
// speedup vs baseline: 1.6936x; 1.6936x over previous
#include <cuda_runtime.h>
#include <stdint.h>

#define NANCH 8732
#define NCLS 21
#define TOPK 200
#define CONF_TH 0.01f
#define NMS_TH 0.045f
#define MAXB 128

// Scratch (no device allocs allowed):
__device__ float g_probsT[(size_t)MAXB * NCLS * NANCH];   // masked softmax probs, [B,C,N]
__device__ float g_boxes[(size_t)MAXB * NANCH * 4];       // decoded corner boxes, [B,N,4]

// ---------------------------------------------------------------------------
// Kernel A: softmax over classes + SSD box decode. One thread per (b,n),
// conf staged through smem for coalesced global loads. (Near HBM roofline.)
// ---------------------------------------------------------------------------
__global__ void __launch_bounds__(256) softmax_decode_kernel(
        const float* __restrict__ loc,
        const float* __restrict__ conf,
        const float* __restrict__ anchors,
        int total) {
    __shared__ float sc[256 * NCLS];
    int base = blockIdx.x * 256;

    int gbase = base * NCLS;
    int navail = min(256 * NCLS, total * NCLS - gbase);
    for (int i = threadIdx.x; i < navail; i += 256)
        sc[i] = conf[gbase + i];
    __syncthreads();

    int idx = base + threadIdx.x;
    if (idx >= total) return;
    int b = idx / NANCH;
    int n = idx - b * NANCH;

    float v[NCLS];
    float mx = -1e30f;
#pragma unroll
    for (int c = 0; c < NCLS; c++) { v[c] = sc[threadIdx.x * NCLS + c]; mx = fmaxf(mx, v[c]); }
    float s = 0.0f;
#pragma unroll
    for (int c = 0; c < NCLS; c++) { v[c] = expf(v[c] - mx); s += v[c]; }
    float inv = 1.0f / s;
#pragma unroll
    for (int c = 0; c < NCLS; c++) {
        float p = v[c] * inv;
        g_probsT[((size_t)b * NCLS + c) * NANCH + n] = (p > CONF_TH) ? p : 0.0f;
    }

    float4 l4 = __ldg((const float4*)(loc) + idx);
    float4 a4 = __ldg((const float4*)(anchors) + n);
    float cx = a4.x + l4.x * 0.1f * a4.z;
    float cy = a4.y + l4.y * 0.1f * a4.w;
    float w  = a4.z * expf(l4.z * 0.2f);
    float h  = a4.w * expf(l4.w * 0.2f);
    float4 bb;
    bb.x = cx - 0.5f * w;
    bb.y = cy - 0.5f * h;
    bb.z = cx + 0.5f * w;
    bb.w = cy + 0.5f * h;
    ((float4*)g_boxes)[idx] = bb;
}

// ---------------------------------------------------------------------------
// Kernel B: per (b, class) task. Radix-select top-200 (per-warp hists),
// bitonic sort, then ON-DEMAND single-warp NMS: keep set as 7 bitmask regs,
// __ffs walk over kept candidates only, broadcast-LDS pivot box, 7 ballots.
// ---------------------------------------------------------------------------
__global__ void __launch_bounds__(256) topk_nms_kernel(float* __restrict__ out) {
    int task = blockIdx.x;
    int b = task / (NCLS - 1);
    int c = task % (NCLS - 1) + 1;   // skip background class 0
    int tid = threadIdx.x;
    int lane = tid & 31, wrp = tid >> 5;

    __shared__ __align__(16) unsigned sbits[NANCH];       // 34928 B
    // overlay: radix phase -> whist[8][256] (8KB) + shist[256] (1KB)
    //          select phase -> sbx4[200] (3200) + sarea[200] (800) + skey[256] (2048)
    __shared__ __align__(16) char ubuf[9216 + 16];
    __shared__ unsigned keepmask[7];
    __shared__ unsigned k_sh, bin_sh, cnt_sh;

    unsigned (*whist)[256] = (unsigned(*)[256])ubuf;
    unsigned* shist = (unsigned*)(ubuf + 8192);
    float4*   sbx4  = (float4*)ubuf;                      // [200]
    float*    sarea = (float*)(ubuf + 3200);              // [200]
    unsigned long long* skey = (unsigned long long*)(ubuf + 4000);  // [256], 8B aligned

    // Load masked scores (coalesced; bit pattern order == value order, all >= 0)
    const float* sp = g_probsT + ((size_t)b * NCLS + c) * NANCH;
    for (int n = tid; n < NANCH; n += 256)
        sbits[n] = __float_as_uint(sp[n]);
    // zero per-warp histograms (2048 words)
    for (int i = tid; i < 2048; i += 256)
        ((unsigned*)ubuf)[i] = 0u;
    if (tid == 0) { k_sh = TOPK; cnt_sh = 0u; bin_sh = 0u; }
    __syncthreads();

    // --- 4-pass radix select over bits [30:23],[22:15],[14:7],[7:0] ---
    // (sign bit is 0 for all nonzero masked probs; pass-3 digit overlaps
    //  bit 7 which is already fixed by the prefix -> harmless, order intact)
    unsigned prefix = 0u, pmask = 0u;
#pragma unroll
    for (int pass = 0; pass < 4; pass++) {
        const int shift = (pass == 0) ? 23 : (pass == 1) ? 15 : (pass == 2) ? 7 : 0;
        unsigned* myh = whist[wrp];
        for (int n = tid; n < NANCH; n += 256) {
            unsigned u = sbits[n];
            if (u != 0u && (u & pmask) == prefix)
                atomicAdd(&myh[(u >> shift) & 255u], 1u);
        }
        __syncthreads();
        // fold 8 copies into shist and re-zero (each thread owns column tid)
        {
            unsigned s = 0;
#pragma unroll
            for (int w = 0; w < 8; w++) { s += whist[w][tid]; whist[w][tid] = 0u; }
            shist[tid] = s;
        }
        __syncthreads();
        if (tid < 32) {
            uint4 h0 = ((const uint4*)shist)[tid * 2];
            uint4 h1 = ((const uint4*)shist)[tid * 2 + 1];
            unsigned local[8] = {h0.x, h0.y, h0.z, h0.w, h1.x, h1.y, h1.z, h1.w};
            unsigned lsum = 0;
#pragma unroll
            for (int j = 0; j < 8; j++) lsum += local[j];
            unsigned ssum = lsum;
#pragma unroll
            for (int off = 1; off < 32; off <<= 1) {
                unsigned vv = __shfl_down_sync(0xffffffffu, ssum, off);
                if (tid + off < 32) ssum += vv;
            }
            unsigned k = k_sh;
            unsigned run = ssum - lsum;        // suffix count beyond this lane's bins
            unsigned fbin = 0u, fk = 0u;
#pragma unroll
            for (int j = 7; j >= 0; j--) {
                unsigned prev = run;
                run += local[j];
                if (run >= k && prev < k) { fbin = (unsigned)(tid * 8 + j); fk = k - prev; }
            }
            unsigned bmax = __reduce_max_sync(0xffffffffu, fbin);
            unsigned kmax = __reduce_max_sync(0xffffffffu, fk);
            if (tid == 0) {
                bin_sh = bmax;                 // rewritten every pass; no reset elsewhere
                if (kmax) k_sh = kmax;
            }
        }
        __syncthreads();
        prefix |= bin_sh << shift;
        pmask  |= 255u << shift;
    }
    unsigned Plo = (prefix > 0u) ? prefix : 1u;   // never collect exact zeros

    // --- collect candidates >= pivot into skey (overlays dead hist region) ---
    skey[tid] = 0ULL;
    __syncthreads();
    for (int n = tid; n < NANCH; n += 256) {
        unsigned u = sbits[n];
        if (u >= Plo) {
            unsigned p = atomicAdd(&cnt_sh, 1u);
            if (p < 256u)
                skey[p] = ((unsigned long long)u << 32) | (unsigned)(~n);
        }
    }
    __syncthreads();

    // --- bitonic sort 256 keys descending (value desc, idx asc on ties) ---
    unsigned long long key = skey[tid];
#pragma unroll
    for (int ks = 2; ks <= 256; ks <<= 1) {
#pragma unroll
        for (int st = ks >> 1; st > 0; st >>= 1) {
            bool up = ((tid & ks) == 0);
            unsigned long long other;
            if (st >= 32) {
                skey[tid] = key;
                __syncthreads();
                other = skey[tid ^ st];
                __syncthreads();
            } else {
                other = __shfl_xor_sync(0xffffffffu, key, st);
            }
            bool iLow = ((tid & st) == 0);
            bool takeMax = (iLow == up);
            bool otherBigger = (other > key);
            if (takeMax == otherBigger) key = other;
        }
    }

    // --- fetch boxes for selected top-200 (skey region dead after this) ---
    float score = 0.f, x1 = 0.f, y1 = 0.f, x2 = 0.f, y2 = 0.f, area = 0.f;
    int keepf = 0;
    if (tid < TOPK) {
        unsigned vb = (unsigned)(key >> 32);
        if (vb != 0u) {
            unsigned n = ~(unsigned)(key & 0xFFFFFFFFu);
            score = __uint_as_float(vb);
            float4 bp = ((const float4*)g_boxes)[(size_t)b * NANCH + n];
            x1 = bp.x; y1 = bp.y; x2 = bp.z; y2 = bp.w;
            area = (x2 - x1) * (y2 - y1);
            keepf = 1;
        }
        float4 bb; bb.x = x1; bb.y = y1; bb.z = x2; bb.w = y2;
        sbx4[tid] = bb;
        sarea[tid] = area;
    }
    {
        unsigned bal = __ballot_sync(0xffffffffu, keepf);
        if (lane == 0 && wrp < 7) keepmask[wrp] = bal;   // tids>=200 have keepf=0
    }
    __syncthreads();

    // --- single-warp on-demand NMS: walk kept candidates only ---
    if (wrp == 0) {
        unsigned keep[7];
#pragma unroll
        for (int t = 0; t < 7; t++) keep[t] = keepmask[t];

        for (int t = 0; t < 7; t++) {
            unsigned rem = keep[t];
            while (rem) {
                int bpos = __ffs(rem) - 1;
                int j = t * 32 + bpos;                 // kept pivot
                float4 pb = sbx4[j];                   // broadcast LDS
                float pa = sarea[j];
#pragma unroll
                for (int tt = 0; tt < 7; tt++) {
                    if (tt >= t) {                     // warp-uniform branch
                        int jj = tt * 32 + lane;
                        float4 ob; float oa;
                        if (jj < TOPK) { ob = sbx4[jj]; oa = sarea[jj]; }
                        else { ob.x = 0.f; ob.y = 0.f; ob.z = -1.f; ob.w = -1.f; oa = 0.f; }
                        float ix1 = fmaxf(pb.x, ob.x);
                        float iy1 = fmaxf(pb.y, ob.y);
                        float ix2 = fminf(pb.z, ob.z);
                        float iy2 = fminf(pb.w, ob.w);
                        float iw = fmaxf(ix2 - ix1, 0.0f);
                        float ih = fmaxf(iy2 - iy1, 0.0f);
                        float inter = iw * ih;
                        float iou = inter / (pa + oa - inter + 1e-12f);
                        unsigned sup = __ballot_sync(0xffffffffu, iou > NMS_TH);
                        if (tt == t) sup &= ~((2u << bpos) - 1u);   // only bits > bpos
                        keep[tt] &= ~sup;
                    }
                }
                rem = keep[t] & ~((2u << bpos) - 1u);
            }
        }
        if (lane < 7) keepmask[lane] = keep[lane];
    }
    __syncthreads();

    // --- pack kept entries to the front (stable) and write output ---
    if (tid < TOPK) {
        unsigned km = keepmask[wrp];
        if ((km >> lane) & 1u) {
            int pos = __popc(km & ((1u << lane) - 1u));
#pragma unroll
            for (int q = 0; q < 6; q++)
                if (q < wrp) pos += __popc(keepmask[q]);
            float* orow = out + ((((size_t)b * NCLS + c) * TOPK) + pos) * 5;
            orow[0] = score; orow[1] = x1; orow[2] = y1; orow[3] = x2; orow[4] = y2;
        }
    }
}

// ---------------------------------------------------------------------------
extern "C" void kernel_launch(void* const* d_in, const int* in_sizes, int n_in,
                              void* d_out, int out_size) {
    const float* loc     = (const float*)d_in[0];  // [B,N,4]
    const float* conf    = (const float*)d_in[1];  // [B,N,21]
    const float* anchors = (const float*)d_in[2];  // [N,4]
    float* out = (float*)d_out;                    // [B,21,200,5]

    int total = in_sizes[0] / 4;          // B*N
    int B = total / NANCH;
    if (B > MAXB) B = MAXB;
    total = B * NANCH;

    cudaMemsetAsync(d_out, 0, (size_t)out_size * sizeof(float), 0);

    softmax_decode_kernel<<<(total + 255) / 256, 256>>>(loc, conf, anchors, total);
    topk_nms_kernel<<<B * (NCLS - 1), 256>>>(out);
}

// round 5
// speedup vs baseline: 2.1108x; 1.2464x over previous
#include <cuda_runtime.h>
#include <stdint.h>

#define NANCH 8732
#define NVEC4 2183            // NANCH / 4 exactly
#define NCLS 21
#define TOPK 200
#define CONF_TH 0.01f
#define NMS_TH 0.045f
#define MAXB 128
#define CANDCAP 1024u

// Scratch (no device allocs allowed):
__device__ float g_probsT[(size_t)MAXB * NCLS * NANCH];   // masked softmax probs, [B,C,N]
__device__ float g_boxes[(size_t)MAXB * NANCH * 4];       // decoded corner boxes, [B,N,4]

// ---------------------------------------------------------------------------
// Kernel A: softmax over classes + SSD box decode. One thread per (b,n),
// conf staged through smem for coalesced global loads. (Near HBM roofline.)
// ---------------------------------------------------------------------------
__global__ void __launch_bounds__(256) softmax_decode_kernel(
        const float* __restrict__ loc,
        const float* __restrict__ conf,
        const float* __restrict__ anchors,
        int total) {
    __shared__ float sc[256 * NCLS];
    int base = blockIdx.x * 256;

    int gbase = base * NCLS;
    int navail = min(256 * NCLS, total * NCLS - gbase);
    for (int i = threadIdx.x; i < navail; i += 256)
        sc[i] = conf[gbase + i];
    __syncthreads();

    int idx = base + threadIdx.x;
    if (idx >= total) return;
    int b = idx / NANCH;
    int n = idx - b * NANCH;

    float v[NCLS];
    float mx = -1e30f;
#pragma unroll
    for (int c = 0; c < NCLS; c++) { v[c] = sc[threadIdx.x * NCLS + c]; mx = fmaxf(mx, v[c]); }
    float s = 0.0f;
#pragma unroll
    for (int c = 0; c < NCLS; c++) { v[c] = expf(v[c] - mx); s += v[c]; }
    float inv = 1.0f / s;
#pragma unroll
    for (int c = 0; c < NCLS; c++) {
        float p = v[c] * inv;
        g_probsT[((size_t)b * NCLS + c) * NANCH + n] = (p > CONF_TH) ? p : 0.0f;
    }

    float4 l4 = __ldg((const float4*)(loc) + idx);
    float4 a4 = __ldg((const float4*)(anchors) + n);
    float cx = a4.x + l4.x * 0.1f * a4.z;
    float cy = a4.y + l4.y * 0.1f * a4.w;
    float w  = a4.z * expf(l4.z * 0.2f);
    float h  = a4.w * expf(l4.w * 0.2f);
    float4 bb;
    bb.x = cx - 0.5f * w;
    bb.y = cy - 0.5f * h;
    bb.z = cx + 0.5f * w;
    bb.w = cy + 0.5f * h;
    ((float4*)g_boxes)[idx] = bb;
}

// ---------------------------------------------------------------------------
// fold 8 per-warp hists -> select pivot bin via warp-0 suffix scan.
// Call with all 256 threads. Updates *bin_sh (always) and *k_sh (if found).
// ---------------------------------------------------------------------------
__device__ __forceinline__ void fold_select(unsigned (*whist)[256], unsigned* shist,
                                            unsigned* k_sh, unsigned* bin_sh, int tid) {
    __syncthreads();                                      // hist writes done
    unsigned s = 0;
#pragma unroll
    for (int w = 0; w < 8; w++) { s += whist[w][tid]; whist[w][tid] = 0u; }
    shist[tid] = s;
    __syncthreads();
    if (tid < 32) {
        uint4 h0 = ((const uint4*)shist)[tid * 2];
        uint4 h1 = ((const uint4*)shist)[tid * 2 + 1];
        unsigned local[8] = {h0.x, h0.y, h0.z, h0.w, h1.x, h1.y, h1.z, h1.w};
        unsigned lsum = 0;
#pragma unroll
        for (int j = 0; j < 8; j++) lsum += local[j];
        unsigned ssum = lsum;
#pragma unroll
        for (int off = 1; off < 32; off <<= 1) {
            unsigned vv = __shfl_down_sync(0xffffffffu, ssum, off);
            if (tid + off < 32) ssum += vv;
        }
        unsigned k = *k_sh;
        unsigned run = ssum - lsum;            // suffix count beyond this lane's bins
        unsigned fbin = 0u, fk = 0u;
#pragma unroll
        for (int j = 7; j >= 0; j--) {
            unsigned prev = run;
            run += local[j];
            if (run >= k && prev < k) { fbin = (unsigned)(tid * 8 + j); fk = k - prev; }
        }
        unsigned bmax = __reduce_max_sync(0xffffffffu, fbin);
        unsigned kmax = __reduce_max_sync(0xffffffffu, fk);
        if (tid == 0) {
            *bin_sh = bmax;                    // 0 <=> nothing found (degenerate)
            if (kmax) *k_sh = kmax;
        }
    }
    __syncthreads();
}

// ---------------------------------------------------------------------------
// Kernel B: per (b, class) task. All nonzero scores have bits[31:27]=00111
// (p in (0.01, 1]), so radix-select over bits [26:19],[18:11],[10:3].
// Pass1 splits: >bin0 -> skey directly; ==bin0 -> cand list (+next hist).
// Exact 256-key sort resolves the [2:0] slack. Single-warp on-demand NMS
// with chunk-skip. Division kept bit-identical to the reference.
// ---------------------------------------------------------------------------
__global__ void __launch_bounds__(256, 6) topk_nms_kernel(float* __restrict__ out) {
    int task = blockIdx.x;
    int b = task / (NCLS - 1);
    int c = task % (NCLS - 1) + 1;   // skip background class 0
    int tid = threadIdx.x;
    int lane = tid & 31, wrp = tid >> 5;

    // [0,8192)      whist[8][256]        (reused later: sbx4[200]+sarea[200])
    // [8192,9216)   shist[256]
    // [9216,17408)  cand[1024] (u64)
    // [17408,19456) skey[256]  (u64)
    __shared__ __align__(16) char ubuf[19456];
    __shared__ unsigned keepmask[7];
    __shared__ unsigned k_sh, bin_sh, scnt, ccnt;

    unsigned (*whist)[256] = (unsigned(*)[256])ubuf;
    unsigned* shist = (unsigned*)(ubuf + 8192);
    unsigned long long* cand = (unsigned long long*)(ubuf + 9216);
    unsigned long long* skey = (unsigned long long*)(ubuf + 17408);
    float4*   sbx4  = (float4*)ubuf;                      // [200]
    float*    sarea = (float*)(ubuf + 3200);              // [200]

    for (int i = tid; i < 2048; i += 256)
        ((unsigned*)ubuf)[i] = 0u;                        // zero whist
    skey[tid] = 0ULL;
    if (tid == 0) { k_sh = TOPK; scnt = 0u; ccnt = 0u; bin_sh = 0u; }
    __syncthreads();

    const unsigned* spu =
        (const unsigned*)(g_probsT + ((size_t)b * NCLS + c) * NANCH);
    const uint4* spu4 = (const uint4*)spu;                // row is 16B aligned (8732%4==0)

    // --- pass 0: hist over bits[26:19] (global scan #1) ---
    {
        unsigned* myh = whist[wrp];
        for (int i = tid; i < NVEC4; i += 256) {
            uint4 v = __ldg(spu4 + i);
            if (v.x) atomicAdd(&myh[(v.x >> 19) & 255u], 1u);
            if (v.y) atomicAdd(&myh[(v.y >> 19) & 255u], 1u);
            if (v.z) atomicAdd(&myh[(v.z >> 19) & 255u], 1u);
            if (v.w) atomicAdd(&myh[(v.w >> 19) & 255u], 1u);
        }
    }
    fold_select(whist, shist, &k_sh, &bin_sh, tid);
    unsigned bin0 = bin_sh;

    // --- pass 1: split scan (global scan #2): >bin0 -> skey, ==bin0 -> cand+hist1
    {
        unsigned* myh = whist[wrp];
        for (int i = tid; i < NVEC4; i += 256) {
            uint4 v = __ldg(spu4 + i);
            unsigned us[4] = {v.x, v.y, v.z, v.w};
#pragma unroll
            for (int q = 0; q < 4; q++) {
                unsigned u = us[q];
                if (!u) continue;
                int n = 4 * i + q;
                unsigned d = (u >> 19) & 255u;
                if (d > bin0) {
                    unsigned p = atomicAdd(&scnt, 1u);
                    if (p < 256u)
                        skey[p] = ((unsigned long long)u << 32) | (unsigned)(~n);
                } else if (d == bin0) {
                    unsigned q2 = atomicAdd(&ccnt, 1u);
                    if (q2 < CANDCAP)
                        cand[q2] = ((unsigned long long)u << 32) | (unsigned)(~n);
                    atomicAdd(&myh[(u >> 11) & 255u], 1u);
                }
            }
        }
    }
    fold_select(whist, shist, &k_sh, &bin_sh, tid);
    unsigned bin1 = bin_sh;
    unsigned cc = ccnt;                       // stable: written before fold's barrier
    bool uselist = (cc <= CANDCAP);
    unsigned prefix = (bin0 << 19) | (bin1 << 11);
    unsigned pmask  = (255u << 19) | (255u << 11);

    // --- pass 2: hist over bits[10:3] among prefix-matching candidates ---
    {
        unsigned* myh = whist[wrp];
        if (uselist) {
            for (unsigned i = tid; i < cc; i += 256) {
                unsigned u = (unsigned)(cand[i] >> 32);
                if ((u & pmask) == prefix) atomicAdd(&myh[(u >> 3) & 255u], 1u);
            }
        } else {
            for (int i = tid; i < NVEC4; i += 256) {
                uint4 v = __ldg(spu4 + i);
                unsigned us[4] = {v.x, v.y, v.z, v.w};
#pragma unroll
                for (int q = 0; q < 4; q++) {
                    unsigned u = us[q];
                    if (u && (u & pmask) == prefix)
                        atomicAdd(&myh[(u >> 3) & 255u], 1u);
                }
            }
        }
    }
    fold_select(whist, shist, &k_sh, &bin_sh, tid);
    unsigned bin2 = bin_sh;
    // Pivot floor (bits [2:0] = 0): collect a tiny superset; sort resolves it.
    unsigned Plo = 0x38000000u | prefix | (bin2 << 3);
    if (bin0 == 0u) Plo = 1u;                 // degenerate: <200 nonzero, all in skey already

    // --- collect remaining (==bin0 candidates with u >= Plo) into skey ---
    if (uselist) {
        for (unsigned i = tid; i < cc; i += 256) {
            unsigned long long kk = cand[i];
            if ((unsigned)(kk >> 32) >= Plo) {
                unsigned p = atomicAdd(&scnt, 1u);
                if (p < 256u) skey[p] = kk;
            }
        }
    } else {
        for (int i = tid; i < NVEC4; i += 256) {
            uint4 v = __ldg(spu4 + i);
            unsigned us[4] = {v.x, v.y, v.z, v.w};
#pragma unroll
            for (int q = 0; q < 4; q++) {
                unsigned u = us[q];
                if (u && ((u >> 19) & 255u) == bin0 && u >= Plo) {
                    int n = 4 * i + q;
                    unsigned p = atomicAdd(&scnt, 1u);
                    if (p < 256u)
                        skey[p] = ((unsigned long long)u << 32) | (unsigned)(~n);
                }
            }
        }
    }
    __syncthreads();

    // --- bitonic sort 256 keys descending (value desc, idx asc on ties) ---
    unsigned long long key = skey[tid];
#pragma unroll
    for (int ks = 2; ks <= 256; ks <<= 1) {
#pragma unroll
        for (int st = ks >> 1; st > 0; st >>= 1) {
            bool up = ((tid & ks) == 0);
            unsigned long long other;
            if (st >= 32) {
                skey[tid] = key;
                __syncthreads();
                other = skey[tid ^ st];
                __syncthreads();
            } else {
                other = __shfl_xor_sync(0xffffffffu, key, st);
            }
            bool iLow = ((tid & st) == 0);
            bool takeMax = (iLow == up);
            bool otherBigger = (other > key);
            if (takeMax == otherBigger) key = other;
        }
    }

    // --- fetch boxes for the true top-200 (whist region dead -> sbx4/sarea) ---
    float score = 0.f, x1 = 0.f, y1 = 0.f, x2 = 0.f, y2 = 0.f, area = 0.f;
    int keepf = 0;
    if (tid < TOPK) {
        unsigned vb = (unsigned)(key >> 32);
        if (vb != 0u) {
            unsigned n = ~(unsigned)(key & 0xFFFFFFFFu);
            score = __uint_as_float(vb);
            float4 bp = ((const float4*)g_boxes)[(size_t)b * NANCH + n];
            x1 = bp.x; y1 = bp.y; x2 = bp.z; y2 = bp.w;
            area = (x2 - x1) * (y2 - y1);
            keepf = 1;
        }
        float4 bb; bb.x = x1; bb.y = y1; bb.z = x2; bb.w = y2;
        sbx4[tid] = bb;
        sarea[tid] = area;
    }
    {
        unsigned bal = __ballot_sync(0xffffffffu, keepf);
        if (lane == 0 && wrp < 7) keepmask[wrp] = bal;
    }
    __syncthreads();

    // --- single-warp on-demand NMS with chunk-skip ---
    if (wrp == 0) {
        unsigned keep[7];
#pragma unroll
        for (int t = 0; t < 7; t++) keep[t] = keepmask[t];

        for (int t = 0; t < 7; t++) {
            unsigned rem = keep[t];
            while (rem) {
                int bpos = __ffs(rem) - 1;
                int j = t * 32 + bpos;                 // kept pivot
                float4 pb = sbx4[j];                   // broadcast LDS
                float pa = sarea[j];
#pragma unroll
                for (int tt = 0; tt < 7; tt++) {
                    if (tt >= t && keep[tt]) {         // warp-uniform skip
                        int jj = tt * 32 + lane;
                        float4 ob; float oa;
                        if (jj < TOPK) { ob = sbx4[jj]; oa = sarea[jj]; }
                        else { ob.x = 0.f; ob.y = 0.f; ob.z = -1.f; ob.w = -1.f; oa = 0.f; }
                        float ix1 = fmaxf(pb.x, ob.x);
                        float iy1 = fmaxf(pb.y, ob.y);
                        float ix2 = fminf(pb.z, ob.z);
                        float iy2 = fminf(pb.w, ob.w);
                        float iw = fmaxf(ix2 - ix1, 0.0f);
                        float ih = fmaxf(iy2 - iy1, 0.0f);
                        float inter = iw * ih;
                        float iou = inter / (pa + oa - inter + 1e-12f);
                        unsigned sup = __ballot_sync(0xffffffffu, iou > NMS_TH);
                        if (tt == t) sup &= ~((2u << bpos) - 1u);   // only bits > bpos
                        keep[tt] &= ~sup;
                    }
                }
                rem = keep[t] & ~((2u << bpos) - 1u);
            }
        }
        if (lane < 7) keepmask[lane] = keep[lane];
    }
    __syncthreads();

    // --- pack kept entries to the front (stable) and write output ---
    if (tid < TOPK) {
        unsigned km = keepmask[wrp];
        if ((km >> lane) & 1u) {
            int pos = __popc(km & ((1u << lane) - 1u));
#pragma unroll
            for (int q = 0; q < 6; q++)
                if (q < wrp) pos += __popc(keepmask[q]);
            float* orow = out + ((((size_t)b * NCLS + c) * TOPK) + pos) * 5;
            orow[0] = score; orow[1] = x1; orow[2] = y1; orow[3] = x2; orow[4] = y2;
        }
    }
}

// ---------------------------------------------------------------------------
extern "C" void kernel_launch(void* const* d_in, const int* in_sizes, int n_in,
                              void* d_out, int out_size) {
    const float* loc     = (const float*)d_in[0];  // [B,N,4]
    const float* conf    = (const float*)d_in[1];  // [B,N,21]
    const float* anchors = (const float*)d_in[2];  // [N,4]
    float* out = (float*)d_out;                    // [B,21,200,5]

    int total = in_sizes[0] / 4;          // B*N
    int B = total / NANCH;
    if (B > MAXB) B = MAXB;
    total = B * NANCH;

    cudaMemsetAsync(d_out, 0, (size_t)out_size * sizeof(float), 0);

    softmax_decode_kernel<<<(total + 255) / 256, 256>>>(loc, conf, anchors, total);
    topk_nms_kernel<<<B * (NCLS - 1), 256>>>(out);
}

// round 6
// speedup vs baseline: 2.2442x; 1.0632x over previous
#include <cuda_runtime.h>
#include <stdint.h>

#define NANCH 8732
#define NVEC4 2183            // NANCH / 4 exactly
#define NVPAD 2304            // 9 * 256: padded loop bound (uniform trip count)
#define NCLS 21
#define TOPK 200
#define CONF_TH 0.01f
#define NMS_TH 0.045f
#define MAXB 128
#define CANDCAP 2048u

// Scratch (no device allocs allowed). probsT stores classes 1..20 only.
__device__ float g_probsT[(size_t)MAXB * (NCLS - 1) * NANCH];   // [B,20,N]
__device__ float g_boxes[(size_t)MAXB * NANCH * 4];             // [B,N,4]

// ---------------------------------------------------------------------------
// Kernel A: softmax over classes + SSD box decode. One thread per (b,n).
// ---------------------------------------------------------------------------
__global__ void __launch_bounds__(256) softmax_decode_kernel(
        const float* __restrict__ loc,
        const float* __restrict__ conf,
        const float* __restrict__ anchors,
        int total) {
    __shared__ float sc[256 * NCLS];
    int base = blockIdx.x * 256;

    int gbase = base * NCLS;
    int navail = min(256 * NCLS, total * NCLS - gbase);
    for (int i = threadIdx.x; i < navail; i += 256)
        sc[i] = conf[gbase + i];
    __syncthreads();

    int idx = base + threadIdx.x;
    if (idx >= total) return;
    int b = idx / NANCH;
    int n = idx - b * NANCH;

    float v[NCLS];
    float mx = -1e30f;
#pragma unroll
    for (int c = 0; c < NCLS; c++) { v[c] = sc[threadIdx.x * NCLS + c]; mx = fmaxf(mx, v[c]); }
    float s = 0.0f;
#pragma unroll
    for (int c = 0; c < NCLS; c++) { v[c] = expf(v[c] - mx); s += v[c]; }
    float inv = 1.0f / s;
#pragma unroll
    for (int c = 1; c < NCLS; c++) {     // class 0 never read downstream
        float p = v[c] * inv;
        g_probsT[((size_t)b * (NCLS - 1) + (c - 1)) * NANCH + n] = (p > CONF_TH) ? p : 0.0f;
    }

    float4 l4 = __ldg((const float4*)(loc) + idx);
    float4 a4 = __ldg((const float4*)(anchors) + n);
    float cx = a4.x + l4.x * 0.1f * a4.z;
    float cy = a4.y + l4.y * 0.1f * a4.w;
    float w  = a4.z * expf(l4.z * 0.2f);
    float h  = a4.w * expf(l4.w * 0.2f);
    float4 bb;
    bb.x = cx - 0.5f * w;
    bb.y = cy - 0.5f * h;
    bb.z = cx + 0.5f * w;
    bb.w = cy + 0.5f * h;
    ((float4*)g_boxes)[idx] = bb;
}

// ---------------------------------------------------------------------------
// Kernel B: per (b, class) task.
//  1) adaptive threshold probe + single collect scan -> cand list (<=2048)
//  2) 3-pass radix select ON THE LIST (bits [26:19],[18:11],[10:3];
//     bits[31:27]=00111 constant for p in (0.01,1])
//  3) exact 256-key bitonic sort (value desc, idx asc), single-warp NMS, pack
// ---------------------------------------------------------------------------
__global__ void __launch_bounds__(256, 6) topk_nms_kernel(float* __restrict__ out) {
    int task = blockIdx.x;
    int b = task / (NCLS - 1);
    int c = task % (NCLS - 1);        // 0..19 -> output class c+1
    int tid = threadIdx.x;
    int lane = tid & 31, wrp = tid >> 5;

    __shared__ __align__(16) unsigned long long cand[CANDCAP];   // 16KB; overlays sbx4/sarea later
    __shared__ __align__(16) unsigned long long skey[256];       // 2KB
    __shared__ __align__(16) unsigned shist[256];                // 1KB
    __shared__ unsigned keepmask[7];
    __shared__ unsigned k_sh, bin_sh, ccnt, scnt;

    float4* sbx4  = (float4*)cand;                 // [200]  (cand dead by then)
    float*  sarea = (float*)(cand + 400);          // [200]

    const uint4* spu4 = (const uint4*)
        (g_probsT + ((size_t)b * (NCLS - 1) + c) * NANCH);

    // ---- 1) adaptive collect: find T with count(u>=T) in [200, 2048] ----
    unsigned lo = 0u, hi = 0x3F800001u, T = 0x3E000000u;   // first probe: 0.125
    unsigned cc = 0u;
    for (int attempt = 0; attempt < 24; attempt++) {
        if (tid == 0) ccnt = 0u;
        __syncthreads();
        for (int i = tid; i < NVPAD; i += 256) {
            uint4 v;
            if (i < NVEC4) v = __ldg(spu4 + i);
            else { v.x = 0u; v.y = 0u; v.z = 0u; v.w = 0u; }
            unsigned us[4] = {v.x, v.y, v.z, v.w};
            int c4 = (us[0] >= T) + (us[1] >= T) + (us[2] >= T) + (us[3] >= T);
            // inclusive warp scan of c4
            int pre = c4;
#pragma unroll
            for (int off = 1; off < 32; off <<= 1) {
                int vv = __shfl_up_sync(0xffffffffu, pre, off);
                if (lane >= off) pre += vv;
            }
            int tot = __shfl_sync(0xffffffffu, pre, 31);
            unsigned basev = 0u;
            if (lane == 31 && tot) basev = atomicAdd(&ccnt, (unsigned)tot);
            basev = __shfl_sync(0xffffffffu, basev, 31);
            unsigned pos = basev + (unsigned)(pre - c4);
#pragma unroll
            for (int q = 0; q < 4; q++) {
                if (us[q] >= T) {
                    if (pos < CANDCAP)
                        cand[pos] = ((unsigned long long)us[q] << 32) |
                                    (unsigned)(~(4 * i + q));
                    pos++;
                }
            }
        }
        __syncthreads();
        cc = ccnt;
        if (cc <= CANDCAP && (cc >= (unsigned)TOPK || T <= 1u)) break;
        if (cc > CANDCAP) lo = T; else hi = T;
        if (hi <= lo + 1u) { T = (lo > 0u) ? lo : 1u; continue; }  // tie pathology
        T = lo + ((hi - lo) >> 1);
        if (T == 0u) T = 1u;
    }
    if (cc > CANDCAP) cc = CANDCAP;   // unreachable for real data (guarded anyway)

    // ---- 2) 3-pass radix select over the list ----
    shist[tid] = 0u;
    if (tid == 0) { k_sh = TOPK; bin_sh = 0u; }
    __syncthreads();

    unsigned prefix = 0u, pmask = 0u, bin0 = 0u;
#pragma unroll
    for (int pass = 0; pass < 3; pass++) {
        const int shift = (pass == 0) ? 19 : (pass == 1) ? 11 : 3;
        for (unsigned i = tid; i < cc; i += 256) {
            unsigned u = (unsigned)(cand[i] >> 32);
            if ((u & pmask) == prefix) atomicAdd(&shist[(u >> shift) & 255u], 1u);
        }
        __syncthreads();
        if (tid < 32) {
            uint4 h0 = ((const uint4*)shist)[tid * 2];
            uint4 h1 = ((const uint4*)shist)[tid * 2 + 1];
            unsigned local[8] = {h0.x, h0.y, h0.z, h0.w, h1.x, h1.y, h1.z, h1.w};
            unsigned lsum = 0;
#pragma unroll
            for (int j = 0; j < 8; j++) lsum += local[j];
            unsigned ssum = lsum;
#pragma unroll
            for (int off = 1; off < 32; off <<= 1) {
                unsigned vv = __shfl_down_sync(0xffffffffu, ssum, off);
                if (tid + off < 32) ssum += vv;
            }
            unsigned k = k_sh;
            unsigned run = ssum - lsum;
            unsigned fbin = 0u, fk = 0u;
#pragma unroll
            for (int j = 7; j >= 0; j--) {
                unsigned prev = run;
                run += local[j];
                if (run >= k && prev < k) { fbin = (unsigned)(tid * 8 + j); fk = k - prev; }
            }
            unsigned bmax = __reduce_max_sync(0xffffffffu, fbin);
            unsigned kmax = __reduce_max_sync(0xffffffffu, fk);
            if (tid == 0) {
                bin_sh = bmax;
                if (kmax) k_sh = kmax;
            }
        }
        __syncthreads();
        unsigned bin = bin_sh;
        if (pass == 0) bin0 = bin;
        prefix |= bin << shift;
        pmask  |= 255u << shift;
        shist[tid] = 0u;                // re-zero for next pass
        __syncthreads();
    }
    unsigned Plo = 0x38000000u | prefix;
    if (bin0 == 0u) Plo = 1u;           // degenerate: <TOPK nonzero, take all

    // ---- collect u >= Plo from list into skey (<=256 incl. slack ties) ----
    skey[tid] = 0ULL;
    if (tid == 0) scnt = 0u;
    __syncthreads();
    unsigned ccPad = (cc + 255u) & ~255u;
    for (unsigned i = tid; i < ccPad; i += 256) {
        unsigned long long kk = (i < cc) ? cand[i] : 0ULL;
        bool pred = ((unsigned)(kk >> 32) >= Plo);
        unsigned mask = __ballot_sync(0xffffffffu, pred);
        if (mask) {
            int leader = __ffs(mask) - 1;
            unsigned basev = 0u;
            if (lane == leader) basev = atomicAdd(&scnt, (unsigned)__popc(mask));
            basev = __shfl_sync(0xffffffffu, basev, leader);
            if (pred) {
                unsigned pos = basev + (unsigned)__popc(mask & ((1u << lane) - 1u));
                if (pos < 256u) skey[pos] = kk;
            }
        }
    }
    __syncthreads();

    // ---- 3) bitonic sort 256 keys descending (value desc, idx asc) ----
    unsigned long long key = skey[tid];
#pragma unroll
    for (int ks = 2; ks <= 256; ks <<= 1) {
#pragma unroll
        for (int st = ks >> 1; st > 0; st >>= 1) {
            bool up = ((tid & ks) == 0);
            unsigned long long other;
            if (st >= 32) {
                skey[tid] = key;
                __syncthreads();
                other = skey[tid ^ st];
                __syncthreads();
            } else {
                other = __shfl_xor_sync(0xffffffffu, key, st);
            }
            bool iLow = ((tid & st) == 0);
            bool takeMax = (iLow == up);
            bool otherBigger = (other > key);
            if (takeMax == otherBigger) key = other;
        }
    }

    // ---- fetch boxes for the true top-200 (cand region dead -> sbx4/sarea) ----
    float score = 0.f, x1 = 0.f, y1 = 0.f, x2 = 0.f, y2 = 0.f, area = 0.f;
    int keepf = 0;
    if (tid < TOPK) {
        unsigned vb = (unsigned)(key >> 32);
        if (vb != 0u) {
            unsigned n = ~(unsigned)(key & 0xFFFFFFFFu);
            score = __uint_as_float(vb);
            float4 bp = ((const float4*)g_boxes)[(size_t)b * NANCH + n];
            x1 = bp.x; y1 = bp.y; x2 = bp.z; y2 = bp.w;
            area = (x2 - x1) * (y2 - y1);
            keepf = 1;
        }
        float4 bb; bb.x = x1; bb.y = y1; bb.z = x2; bb.w = y2;
        sbx4[tid] = bb;
        sarea[tid] = area;
    }
    {
        unsigned bal = __ballot_sync(0xffffffffu, keepf);
        if (lane == 0 && wrp < 7) keepmask[wrp] = bal;
    }
    __syncthreads();

    // ---- single-warp on-demand NMS with chunk-skip ----
    if (wrp == 0) {
        unsigned keep[7];
#pragma unroll
        for (int t = 0; t < 7; t++) keep[t] = keepmask[t];

        for (int t = 0; t < 7; t++) {
            unsigned rem = keep[t];
            while (rem) {
                int bpos = __ffs(rem) - 1;
                int j = t * 32 + bpos;                 // kept pivot
                float4 pb = sbx4[j];                   // broadcast LDS
                float pa = sarea[j];
#pragma unroll
                for (int tt = 0; tt < 7; tt++) {
                    if (tt >= t && keep[tt]) {         // warp-uniform skip
                        int jj = tt * 32 + lane;
                        float4 ob; float oa;
                        if (jj < TOPK) { ob = sbx4[jj]; oa = sarea[jj]; }
                        else { ob.x = 0.f; ob.y = 0.f; ob.z = -1.f; ob.w = -1.f; oa = 0.f; }
                        float ix1 = fmaxf(pb.x, ob.x);
                        float iy1 = fmaxf(pb.y, ob.y);
                        float ix2 = fminf(pb.z, ob.z);
                        float iy2 = fminf(pb.w, ob.w);
                        float iw = fmaxf(ix2 - ix1, 0.0f);
                        float ih = fmaxf(iy2 - iy1, 0.0f);
                        float inter = iw * ih;
                        float iou = inter / (pa + oa - inter + 1e-12f);
                        unsigned sup = __ballot_sync(0xffffffffu, iou > NMS_TH);
                        if (tt == t) sup &= ~((2u << bpos) - 1u);   // only bits > bpos
                        keep[tt] &= ~sup;
                    }
                }
                rem = keep[t] & ~((2u << bpos) - 1u);
            }
        }
        if (lane < 7) keepmask[lane] = keep[lane];
    }
    __syncthreads();

    // ---- pack kept entries to the front (stable) and write output ----
    if (tid < TOPK) {
        unsigned km = keepmask[wrp];
        if ((km >> lane) & 1u) {
            int pos = __popc(km & ((1u << lane) - 1u));
#pragma unroll
            for (int q = 0; q < 6; q++)
                if (q < wrp) pos += __popc(keepmask[q]);
            float* orow = out + ((((size_t)b * NCLS + (c + 1)) * TOPK) + pos) * 5;
            orow[0] = score; orow[1] = x1; orow[2] = y1; orow[3] = x2; orow[4] = y2;
        }
    }
}

// ---------------------------------------------------------------------------
extern "C" void kernel_launch(void* const* d_in, const int* in_sizes, int n_in,
                              void* d_out, int out_size) {
    const float* loc     = (const float*)d_in[0];  // [B,N,4]
    const float* conf    = (const float*)d_in[1];  // [B,N,21]
    const float* anchors = (const float*)d_in[2];  // [N,4]
    float* out = (float*)d_out;                    // [B,21,200,5]

    int total = in_sizes[0] / 4;          // B*N
    int B = total / NANCH;
    if (B > MAXB) B = MAXB;
    total = B * NANCH;

    cudaMemsetAsync(d_out, 0, (size_t)out_size * sizeof(float), 0);

    softmax_decode_kernel<<<(total + 255) / 256, 256>>>(loc, conf, anchors, total);
    topk_nms_kernel<<<B * (NCLS - 1), 256>>>(out);
}

// round 7
// speedup vs baseline: 2.8495x; 1.2697x over previous
#include <cuda_runtime.h>
#include <stdint.h>

#define NANCH 8732
#define NVEC4 2183            // NANCH / 4 exactly
#define NVPAD 2304            // 9 * 256: padded loop bound (uniform trip count)
#define NCLS 21
#define TOPK 200
#define CONF_TH 0.01f
#define NMS_TH 0.045f
#define MAXB 128
#define CANDCAP 2048u
#define TPC 4                 // tasks per CTA

// Scratch (no device allocs allowed). probsT stores classes 1..20 only.
__device__ float g_probsT[(size_t)MAXB * (NCLS - 1) * NANCH];   // [B,20,N]
__device__ float g_boxes[(size_t)MAXB * NANCH * 4];             // [B,N,4]

// ---------------------------------------------------------------------------
// Kernel A: softmax over classes + SSD box decode. One thread per (b,n).
// ---------------------------------------------------------------------------
__global__ void __launch_bounds__(256) softmax_decode_kernel(
        const float* __restrict__ loc,
        const float* __restrict__ conf,
        const float* __restrict__ anchors,
        int total) {
    __shared__ float sc[256 * NCLS];
    int base = blockIdx.x * 256;

    int gbase = base * NCLS;
    int navail = min(256 * NCLS, total * NCLS - gbase);
    for (int i = threadIdx.x; i < navail; i += 256)
        sc[i] = conf[gbase + i];
    __syncthreads();

    int idx = base + threadIdx.x;
    if (idx >= total) return;
    int b = idx / NANCH;
    int n = idx - b * NANCH;

    float v[NCLS];
    float mx = -1e30f;
#pragma unroll
    for (int c = 0; c < NCLS; c++) { v[c] = sc[threadIdx.x * NCLS + c]; mx = fmaxf(mx, v[c]); }
    float s = 0.0f;
#pragma unroll
    for (int c = 0; c < NCLS; c++) { v[c] = expf(v[c] - mx); s += v[c]; }
    float inv = 1.0f / s;
#pragma unroll
    for (int c = 1; c < NCLS; c++) {     // class 0 never read downstream
        float p = v[c] * inv;
        g_probsT[((size_t)b * (NCLS - 1) + (c - 1)) * NANCH + n] = (p > CONF_TH) ? p : 0.0f;
    }

    float4 l4 = __ldg((const float4*)(loc) + idx);
    float4 a4 = __ldg((const float4*)(anchors) + n);
    float cx = a4.x + l4.x * 0.1f * a4.z;
    float cy = a4.y + l4.y * 0.1f * a4.w;
    float w  = a4.z * expf(l4.z * 0.2f);
    float h  = a4.w * expf(l4.w * 0.2f);
    float4 bb;
    bb.x = cx - 0.5f * w;
    bb.y = cy - 0.5f * h;
    bb.z = cx + 0.5f * w;
    bb.w = cy + 0.5f * h;
    ((float4*)g_boxes)[idx] = bb;
}

// ---------------------------------------------------------------------------
// Kernel B: 4 (b,class) tasks per CTA.
//  Per task (8 warps): adaptive-threshold collect -> <=2048 cand list,
//  3-pass radix select on list (bits [26:19],[18:11],[10:3]; bits[31:27]=00111
//  for p in (0.01,1]), exact 256-key bitonic sort -> per-task smem arrays.
//  NMS phase: warps 0..3 run the 4 serial NMS chains CONCURRENTLY.
//  Pack phase: stable compaction + output write per task.
// ---------------------------------------------------------------------------
__global__ void __launch_bounds__(256, 5) topk_nms_kernel(float* __restrict__ out) {
    int tid = threadIdx.x;
    int lane = tid & 31, wrp = tid >> 5;

    __shared__ __align__(16) unsigned long long cand[CANDCAP];   // 16384 B
    __shared__ __align__(16) unsigned long long skey[256];       // 2048 B
    __shared__ __align__(16) unsigned shist[256];                // 1024 B
    __shared__ __align__(16) float4 sbx4[TPC][TOPK];             // 12800 B
    __shared__ float  sarea[TPC][TOPK];                          // 3200 B
    __shared__ float  sscore[TPC][TOPK];                         // 3200 B
    __shared__ unsigned keepmask[TPC][7];
    __shared__ unsigned k_sh, bin_sh, ccnt, scnt;

    // ================= per-task select phase (all 8 warps) =================
#pragma unroll 1
    for (int s = 0; s < TPC; s++) {
        int task = blockIdx.x * TPC + s;
        int b = task / (NCLS - 1);
        int c = task % (NCLS - 1);        // 0..19 -> output class c+1

        const uint4* spu4 = (const uint4*)
            (g_probsT + ((size_t)b * (NCLS - 1) + c) * NANCH);

        // ---- 1) adaptive collect: count(u>=T) in [200, 2048] ----
        unsigned lo = 0u, hi = 0x3F800001u, T = 0x3E000000u;   // first probe 0.125
        unsigned cc = 0u;
        for (int attempt = 0; attempt < 24; attempt++) {
            if (tid == 0) ccnt = 0u;
            __syncthreads();
            for (int i = tid; i < NVPAD; i += 256) {
                uint4 v;
                if (i < NVEC4) v = __ldg(spu4 + i);
                else { v.x = 0u; v.y = 0u; v.z = 0u; v.w = 0u; }
                unsigned us[4] = {v.x, v.y, v.z, v.w};
                int c4 = (us[0] >= T) + (us[1] >= T) + (us[2] >= T) + (us[3] >= T);
                int pre = c4;
#pragma unroll
                for (int off = 1; off < 32; off <<= 1) {
                    int vv = __shfl_up_sync(0xffffffffu, pre, off);
                    if (lane >= off) pre += vv;
                }
                int tot = __shfl_sync(0xffffffffu, pre, 31);
                unsigned basev = 0u;
                if (lane == 31 && tot) basev = atomicAdd(&ccnt, (unsigned)tot);
                basev = __shfl_sync(0xffffffffu, basev, 31);
                unsigned pos = basev + (unsigned)(pre - c4);
#pragma unroll
                for (int q = 0; q < 4; q++) {
                    if (us[q] >= T) {
                        if (pos < CANDCAP)
                            cand[pos] = ((unsigned long long)us[q] << 32) |
                                        (unsigned)(~(4 * i + q));
                        pos++;
                    }
                }
            }
            __syncthreads();
            cc = ccnt;
            if (cc <= CANDCAP && (cc >= (unsigned)TOPK || T <= 1u)) break;
            if (cc > CANDCAP) lo = T; else hi = T;
            if (hi <= lo + 1u) { T = (lo > 0u) ? lo : 1u; continue; }
            T = lo + ((hi - lo) >> 1);
            if (T == 0u) T = 1u;
        }
        if (cc > CANDCAP) cc = CANDCAP;   // unreachable for real data

        // ---- 2) 3-pass radix select over the list ----
        shist[tid] = 0u;
        if (tid == 0) { k_sh = TOPK; bin_sh = 0u; }
        __syncthreads();

        unsigned prefix = 0u, pmask = 0u, bin0 = 0u;
#pragma unroll
        for (int pass = 0; pass < 3; pass++) {
            const int shift = (pass == 0) ? 19 : (pass == 1) ? 11 : 3;
            for (unsigned i = tid; i < cc; i += 256) {
                unsigned u = (unsigned)(cand[i] >> 32);
                if ((u & pmask) == prefix) atomicAdd(&shist[(u >> shift) & 255u], 1u);
            }
            __syncthreads();
            if (tid < 32) {
                uint4 h0 = ((const uint4*)shist)[tid * 2];
                uint4 h1 = ((const uint4*)shist)[tid * 2 + 1];
                unsigned local[8] = {h0.x, h0.y, h0.z, h0.w, h1.x, h1.y, h1.z, h1.w};
                unsigned lsum = 0;
#pragma unroll
                for (int j = 0; j < 8; j++) lsum += local[j];
                unsigned ssum = lsum;
#pragma unroll
                for (int off = 1; off < 32; off <<= 1) {
                    unsigned vv = __shfl_down_sync(0xffffffffu, ssum, off);
                    if (tid + off < 32) ssum += vv;
                }
                unsigned k = k_sh;
                unsigned run = ssum - lsum;
                unsigned fbin = 0u, fk = 0u;
#pragma unroll
                for (int j = 7; j >= 0; j--) {
                    unsigned prev = run;
                    run += local[j];
                    if (run >= k && prev < k) { fbin = (unsigned)(tid * 8 + j); fk = k - prev; }
                }
                unsigned bmax = __reduce_max_sync(0xffffffffu, fbin);
                unsigned kmax = __reduce_max_sync(0xffffffffu, fk);
                if (tid == 0) {
                    bin_sh = bmax;
                    if (kmax) k_sh = kmax;
                }
            }
            __syncthreads();
            unsigned bin = bin_sh;
            if (pass == 0) bin0 = bin;
            prefix |= bin << shift;
            pmask  |= 255u << shift;
            shist[tid] = 0u;
            __syncthreads();
        }
        unsigned Plo = 0x38000000u | prefix;
        if (bin0 == 0u) Plo = 1u;           // degenerate: <TOPK nonzero

        // ---- collect u >= Plo from list into skey (<=256 incl. slack) ----
        skey[tid] = 0ULL;
        if (tid == 0) scnt = 0u;
        __syncthreads();
        unsigned ccPad = (cc + 255u) & ~255u;
        for (unsigned i = tid; i < ccPad; i += 256) {
            unsigned long long kk = (i < cc) ? cand[i] : 0ULL;
            bool pred = ((unsigned)(kk >> 32) >= Plo);
            unsigned mask = __ballot_sync(0xffffffffu, pred);
            if (mask) {
                int leader = __ffs(mask) - 1;
                unsigned basev = 0u;
                if (lane == leader) basev = atomicAdd(&scnt, (unsigned)__popc(mask));
                basev = __shfl_sync(0xffffffffu, basev, leader);
                if (pred) {
                    unsigned pos = basev + (unsigned)__popc(mask & ((1u << lane) - 1u));
                    if (pos < 256u) skey[pos] = kk;
                }
            }
        }
        __syncthreads();

        // ---- 3) bitonic sort 256 keys descending (value desc, idx asc) ----
        unsigned long long key = skey[tid];
#pragma unroll
        for (int ks = 2; ks <= 256; ks <<= 1) {
#pragma unroll
            for (int st = ks >> 1; st > 0; st >>= 1) {
                bool up = ((tid & ks) == 0);
                unsigned long long other;
                if (st >= 32) {
                    skey[tid] = key;
                    __syncthreads();
                    other = skey[tid ^ st];
                    __syncthreads();
                } else {
                    other = __shfl_xor_sync(0xffffffffu, key, st);
                }
                bool iLow = ((tid & st) == 0);
                bool takeMax = (iLow == up);
                bool otherBigger = (other > key);
                if (takeMax == otherBigger) key = other;
            }
        }

        // ---- stash this task's top-200 into per-task smem ----
        int keepf = 0;
        if (tid < TOPK) {
            float score = 0.f, x1 = 0.f, y1 = 0.f, x2 = 0.f, y2 = 0.f, area = 0.f;
            unsigned vb = (unsigned)(key >> 32);
            if (vb != 0u) {
                unsigned n = ~(unsigned)(key & 0xFFFFFFFFu);
                score = __uint_as_float(vb);
                float4 bp = ((const float4*)g_boxes)[(size_t)b * NANCH + n];
                x1 = bp.x; y1 = bp.y; x2 = bp.z; y2 = bp.w;
                area = (x2 - x1) * (y2 - y1);
                keepf = 1;
            }
            float4 bb; bb.x = x1; bb.y = y1; bb.z = x2; bb.w = y2;
            sbx4[s][tid] = bb;
            sarea[s][tid] = area;
            sscore[s][tid] = score;
        }
        {
            unsigned bal = __ballot_sync(0xffffffffu, keepf);
            if (lane == 0 && wrp < 7) keepmask[s][wrp] = bal;
        }
        __syncthreads();   // also protects cand/shist/counters reuse next task
    }

    // ============ NMS phase: warps 0..3 run 4 serial NMS concurrently =======
    if (wrp < TPC) {
        const int s = wrp;
        unsigned keep[7];
#pragma unroll
        for (int t = 0; t < 7; t++) keep[t] = keepmask[s][t];

        for (int t = 0; t < 7; t++) {
            unsigned rem = keep[t];
            while (rem) {
                int bpos = __ffs(rem) - 1;
                int j = t * 32 + bpos;                 // kept pivot
                float4 pb = sbx4[s][j];                // broadcast LDS
                float pa = sarea[s][j];
#pragma unroll
                for (int tt = 0; tt < 7; tt++) {
                    if (tt >= t && keep[tt]) {         // warp-uniform skip
                        int jj = tt * 32 + lane;
                        float4 ob; float oa;
                        if (jj < TOPK) { ob = sbx4[s][jj]; oa = sarea[s][jj]; }
                        else { ob.x = 0.f; ob.y = 0.f; ob.z = -1.f; ob.w = -1.f; oa = 0.f; }
                        float ix1 = fmaxf(pb.x, ob.x);
                        float iy1 = fmaxf(pb.y, ob.y);
                        float ix2 = fminf(pb.z, ob.z);
                        float iy2 = fminf(pb.w, ob.w);
                        float iw = fmaxf(ix2 - ix1, 0.0f);
                        float ih = fmaxf(iy2 - iy1, 0.0f);
                        float inter = iw * ih;
                        float iou = inter / (pa + oa - inter + 1e-12f);
                        unsigned sup = __ballot_sync(0xffffffffu, iou > NMS_TH);
                        if (tt == t) sup &= ~((2u << bpos) - 1u);   // only bits > bpos
                        keep[tt] &= ~sup;
                    }
                }
                rem = keep[t] & ~((2u << bpos) - 1u);
            }
        }
        if (lane < 7) keepmask[s][lane] = keep[lane];
    }
    __syncthreads();

    // ============ pack phase: stable compaction + output write ==============
#pragma unroll
    for (int s = 0; s < TPC; s++) {
        int task = blockIdx.x * TPC + s;
        int b = task / (NCLS - 1);
        int c = task % (NCLS - 1);
        if (tid < TOPK) {
            unsigned km = keepmask[s][wrp];
            if ((km >> lane) & 1u) {
                int pos = __popc(km & ((1u << lane) - 1u));
#pragma unroll
                for (int q = 0; q < 6; q++)
                    if (q < wrp) pos += __popc(keepmask[s][q]);
                float4 bb = sbx4[s][tid];
                float* orow = out + ((((size_t)b * NCLS + (c + 1)) * TOPK) + pos) * 5;
                orow[0] = sscore[s][tid];
                orow[1] = bb.x; orow[2] = bb.y; orow[3] = bb.z; orow[4] = bb.w;
            }
        }
    }
}

// ---------------------------------------------------------------------------
extern "C" void kernel_launch(void* const* d_in, const int* in_sizes, int n_in,
                              void* d_out, int out_size) {
    const float* loc     = (const float*)d_in[0];  // [B,N,4]
    const float* conf    = (const float*)d_in[1];  // [B,N,21]
    const float* anchors = (const float*)d_in[2];  // [N,4]
    float* out = (float*)d_out;                    // [B,21,200,5]

    int total = in_sizes[0] / 4;          // B*N
    int B = total / NANCH;
    if (B > MAXB) B = MAXB;
    total = B * NANCH;

    cudaMemsetAsync(d_out, 0, (size_t)out_size * sizeof(float), 0);

    softmax_decode_kernel<<<(total + 255) / 256, 256>>>(loc, conf, anchors, total);
    int ntask = B * (NCLS - 1);                    // divisible by 4 (20 | ntask)
    topk_nms_kernel<<<ntask / TPC, 256>>>(out);
}